// round 6
// baseline (speedup 1.0000x reference)
#include <cuda_runtime.h>
#include <cuda_bf16.h>
#include <cstdint>
#include <math.h>

#define BB   32
#define TT_  2048
#define CIN  80
#define HCH  256
#define KTOT 240            // K = CIN*3

// scratch (device globals: no allocation allowed)
__device__ float          g_y[TT_*BB*HCH];      // conv out (T,B,H), 64MB
__device__ unsigned short g_xs[3u*BB*CIN*TT_];  // x bf16 limbs, [l][b][c][t], 31.5MB
__device__ __align__(16) unsigned int g_wf[92160]; // w fragment images [hh][kc][ks][nf][l][lane][r]
__device__ double g_sum[HCH];
__device__ double g_sumsq[HCH];
__device__ float  g_mean[HCH];
__device__ float  g_rs[HCH];

__device__ __forceinline__ uint32_t smem_u32(const void* p){
    uint32_t a; asm("{ .reg .u64 t; cvta.to.shared.u64 t, %1; cvt.u32.u64 %0, t; }" : "=r"(a) : "l"(p));
    return a;
}
__device__ __forceinline__ void lds128(uint32_t* r, uint32_t addr){
    asm volatile("ld.shared.v4.b32 {%0,%1,%2,%3}, [%4];"
        : "=r"(r[0]), "=r"(r[1]), "=r"(r[2]), "=r"(r[3]) : "r"(addr));
}
__device__ __forceinline__ void lds64(uint32_t* r, uint32_t addr){
    asm volatile("ld.shared.v2.b32 {%0,%1}, [%2];"
        : "=r"(r[0]), "=r"(r[1]) : "r"(addr));
}
__device__ __forceinline__ void mma_bf16(float* c, const uint32_t* a, const uint32_t* b){
    asm volatile("mma.sync.aligned.m16n8k16.row.col.f32.bf16.bf16.f32 "
        "{%0,%1,%2,%3}, {%4,%5,%6,%7}, {%8,%9}, {%0,%1,%2,%3};"
        : "+f"(c[0]), "+f"(c[1]), "+f"(c[2]), "+f"(c[3])
        : "r"(a[0]), "r"(a[1]), "r"(a[2]), "r"(a[3]), "r"(b[0]), "r"(b[1]));
}

__device__ __forceinline__ unsigned short bsplit(float x, int s){
    __nv_bfloat16 b0 = __float2bfloat16(x);
    if (s == 0) return __bfloat16_as_ushort(b0);
    float r1 = x - __bfloat162float(b0);
    __nv_bfloat16 b1 = __float2bfloat16(r1);
    if (s == 1) return __bfloat16_as_ushort(b1);
    float r2 = r1 - __bfloat162float(b1);
    return __bfloat16_as_ushort(__float2bfloat16(r2));
}

// ---------------- prep: split+transpose x -> g_xs[l][b][c][t] ----------------
__global__ void prep_x_kernel(const float* __restrict__ x){
    extern __shared__ unsigned short st[];      // [3][CIN][136]
    int b  = blockIdx.y;
    int t0 = blockIdx.x * 128;
    int tid = threadIdx.x;
    for (int i = tid; i < 128*CIN; i += 256){
        int tl = i / CIN, c = i - tl*CIN;
        float v = x[((size_t)b*TT_ + t0 + tl)*CIN + c];
        #pragma unroll
        for (int s = 0; s < 3; ++s) st[(s*CIN + c)*136 + tl] = bsplit(v, s);
    }
    __syncthreads();
    for (int i = tid; i < 3*CIN*64; i += 256){
        int r = i >> 6, col = i & 63;
        int s = r / CIN, c = r - s*CIN;
        uint32_t lo = st[r*136 + col*2], hi = st[r*136 + col*2 + 1];
        uint32_t* dst = (uint32_t*)g_xs;
        size_t e = (((size_t)s*BB + b)*CIN + c)*TT_ + t0;
        dst[e/2 + col] = (hi << 16) | lo;
    }
}

// ---------------- prep: w -> fragment-ordered bf16 limb images, zero BN sums ----------------
// u32 index: ((((hh*3+kc)*5+ks)*16+nf)*3+l)*64 + lane*2 + r
__global__ void prep_w_kernel(const float* __restrict__ w){
    int i = blockIdx.x*256 + threadIdx.x;
    if (i < HCH){ g_sum[i] = 0.0; g_sumsq[i] = 0.0; }
    if (i >= 92160) return;
    int r    = i & 1;
    int lane = (i >> 1) & 31;
    int rest = i >> 6;
    int l  = rest % 3;  rest /= 3;
    int nf = rest & 15; rest >>= 4;
    int ks = rest % 5;  rest /= 5;
    int kc = rest % 3;
    int hh = rest / 3;
    int n  = hh*128 + nf*8 + (lane >> 2);
    int k0 = kc*80 + ks*16 + (lane & 3)*2 + r*8;
    int c0 = (k0*171) >> 9, kk0 = k0 - 3*c0;
    int k1 = k0 + 1;
    int c1 = (k1*171) >> 9, kk1 = k1 - 3*c1;
    uint32_t v0 = bsplit(w[(size_t)n*KTOT + c0*3 + kk0], l);
    uint32_t v1 = bsplit(w[(size_t)n*KTOT + c1*3 + kk1], l);
    g_wf[i] = v0 | (v1 << 16);
}

// ---------------- conv via mma.sync bf16 6-GEMM limb emulation ----------------
// CTA: 256 thr (8 warps, 2m x 4n of 64x32), tile 128m x 128n, K in 3 chunks of 80
#define STG_US (3*28*132)           // staging ushorts
#define A_OFF  22528                // bytes (staging 22176 rounded up)
#define A_SZ   61440                // 5*8*3*512
#define B_OFF  (A_OFF + A_SZ)
#define B_SZ   61440                // 5*16*3*256
#define SMEM_CONV (B_OFF + B_SZ)

__global__ void __launch_bounds__(256) conv_mma_kernel(const float* __restrict__ bias){
    extern __shared__ char smem[];
    unsigned short* stage = (unsigned short*)smem;
    const uint32_t sb = smem_u32(smem);
    const int tid = threadIdx.x, lane = tid & 31, w = tid >> 5;
    const int wm = w >> 2, wn = w & 3;
    const int t0 = blockIdx.x * 128;
    const int hh = blockIdx.y;
    const int b  = blockIdx.z;

    float acc[4][4][4];
    #pragma unroll
    for (int mf = 0; mf < 4; ++mf)
        #pragma unroll
        for (int nf = 0; nf < 4; ++nf)
            #pragma unroll
            for (int q = 0; q < 4; ++q) acc[mf][nf][q] = 0.f;

    for (int kc = 0; kc < 3; ++kc){
        const int cbase = (kc*80)/3;
        // --- fill staging (x limbs, t0-1 .. t0+129) + B fragments ---
        for (int i = tid; i < STG_US; i += 256){
            int j = i % 132; int row = i / 132;
            int l = row / 28, ci = row - l*28;
            int c = cbase + ci, t = t0 - 1 + j;
            unsigned short v = 0;
            if (c < CIN && j < 131 && t >= 0 && t < TT_)
                v = g_xs[(((size_t)l*BB + b)*CIN + c)*TT_ + t];
            stage[i] = v;
        }
        {
            const float4* src = (const float4*)g_wf + (size_t)(hh*3 + kc)*3840;
            float4* dst = (float4*)(smem + B_OFF);
            #pragma unroll 5
            for (int i = tid; i < 3840; i += 256) dst[i] = src[i];
        }
        __syncthreads();
        // --- build A fragments from staging ---
        for (int i = tid; i < 15360; i += 256){
            int r = i & 3;
            int ln = (i >> 2) & 31;
            int rest = i >> 7;
            int l = rest % 3; rest /= 3;
            int mf = rest & 7;
            int ks = rest >> 3;
            int m  = mf*16 + (ln >> 2) + (r & 1)*8;
            int k0 = kc*80 + ks*16 + (ln & 3)*2 + (r >> 1)*8;
            int c0 = (k0*171) >> 9, kk0 = k0 - 3*c0;
            int k1 = k0 + 1;
            int c1 = (k1*171) >> 9, kk1 = k1 - 3*c1;
            uint32_t v0 = stage[(l*28 + (c0 - cbase))*132 + m + kk0];
            uint32_t v1 = stage[(l*28 + (c1 - cbase))*132 + m + kk1];
            *(uint32_t*)(smem + A_OFF + (size_t)i*4) = v0 | (v1 << 16);
        }
        __syncthreads();
        // --- mainloop: 5 ksteps x (64 + 32) MMAs per warp ---
        #pragma unroll
        for (int ks = 0; ks < 5; ++ks){
            uint32_t A0[4][4], A1[4][4], B0[4][2], B1[4][2];
            #pragma unroll
            for (int mf = 0; mf < 4; ++mf){
                uint32_t base = sb + A_OFF + (((ks*8 + wm*4 + mf)*3)*512u) + lane*16;
                lds128(A0[mf], base);
                lds128(A1[mf], base + 512);
            }
            #pragma unroll
            for (int nf = 0; nf < 4; ++nf){
                uint32_t base = sb + B_OFF + (((ks*16 + wn*4 + nf)*3)*256u) + lane*8;
                lds64(B0[nf], base);
                lds64(B1[nf], base + 256);
            }
            #pragma unroll
            for (int mf = 0; mf < 4; ++mf)
                #pragma unroll
                for (int nf = 0; nf < 4; ++nf){
                    mma_bf16(acc[mf][nf], A0[mf], B0[nf]);
                    mma_bf16(acc[mf][nf], A0[mf], B1[nf]);
                    mma_bf16(acc[mf][nf], A1[mf], B0[nf]);
                    mma_bf16(acc[mf][nf], A1[mf], B1[nf]);
                }
            uint32_t A2[4][4], B2[4][2];
            #pragma unroll
            for (int mf = 0; mf < 4; ++mf)
                lds128(A2[mf], sb + A_OFF + (((ks*8 + wm*4 + mf)*3)*512u) + 1024 + lane*16);
            #pragma unroll
            for (int nf = 0; nf < 4; ++nf)
                lds64(B2[nf], sb + B_OFF + (((ks*16 + wn*4 + nf)*3)*256u) + 512 + lane*8);
            #pragma unroll
            for (int mf = 0; mf < 4; ++mf)
                #pragma unroll
                for (int nf = 0; nf < 4; ++nf){
                    mma_bf16(acc[mf][nf], A0[mf], B2[nf]);
                    mma_bf16(acc[mf][nf], A2[mf], B0[nf]);
                }
        }
        __syncthreads();
    }

    // --- epilogue: acc + bias -> g_y ---
    const int rbase = t0 + wm*64;
    const int hbase = hh*128 + wn*32;
    #pragma unroll
    for (int mf = 0; mf < 4; ++mf){
        int m0 = rbase + mf*16 + (lane >> 2);
        #pragma unroll
        for (int nf = 0; nf < 4; ++nf){
            int n = hbase + nf*8 + (lane & 3)*2;
            float2 bv = *(const float2*)(bias + n);
            float2 o0 = make_float2(acc[mf][nf][0] + bv.x, acc[mf][nf][1] + bv.y);
            float2 o1 = make_float2(acc[mf][nf][2] + bv.x, acc[mf][nf][3] + bv.y);
            *(float2*)(g_y + ((size_t)m0*BB + b)*HCH + n)       = o0;
            *(float2*)(g_y + ((size_t)(m0+8)*BB + b)*HCH + n)   = o1;
        }
    }
}

// ---------------- BN stats pass ----------------
__global__ void bn_stats_kernel(){
    int h = threadIdx.x;
    size_t r0 = (size_t)blockIdx.x * 128;
    const float* yp = g_y + r0*HCH + h;
    float s = 0.f, q = 0.f;
    #pragma unroll 4
    for (int i = 0; i < 128; ++i){
        float v = yp[(size_t)i*HCH];
        s += v; q += v*v;
    }
    atomicAdd(&g_sum[h], (double)s);
    atomicAdd(&g_sumsq[h], (double)q);
}

// ---------------- BN finalize ----------------
__global__ void finalize_kernel(){
    int h = threadIdx.x;
    const double n = (double)(TT_*BB);
    double mu  = g_sum[h] / n;
    double var = g_sumsq[h] / n - mu*mu;
    g_mean[h] = (float)mu;
    g_rs[h]   = (float)(1.0 / sqrt(var + 1e-5));
}

// ---------------- LIF recurrence (unchanged from R4) ----------------
#define CHUNK 128
#define WARM  96
#define NCHUNK (TT_/CHUNK)
__global__ void __launch_bounds__(256) lif_kernel(const float* __restrict__ gamma,
                                                  const float* __restrict__ beta,
                                                  float* __restrict__ out){
    int g    = blockIdx.x*256 + threadIdx.x;
    int lane = g & (BB*HCH - 1);
    int chunk = g >> 13;
    int h = lane & 255;

    float mu = g_mean[h], rs = g_rs[h], ga = gamma[h], be = beta[h];
    int tstart = chunk * CHUNK;
    int tw = (chunk == 0) ? 0 : tstart - WARM;
    int tend = tstart + CHUNK;

    const float* yp = g_y + lane;
    float* op = out + lane;
    float v = 0.f;

    float cur[8], nxt[8];
    #pragma unroll
    for (int j = 0; j < 8; ++j) cur[j] = yp[(size_t)(tw + j)*(BB*HCH)];

    for (int t0v = tw; t0v < tend; t0v += 8){
        int tn = t0v + 8;
        if (tn < tend){
            #pragma unroll
            for (int j = 0; j < 8; ++j) nxt[j] = yp[(size_t)(tn + j)*(BB*HCH)];
        }
        bool do_store = (t0v >= tstart);
        #pragma unroll
        for (int j = 0; j < 8; ++j){
            float yn = fmaf((cur[j] - mu)*rs, ga, be);
            v = fmaf(v, 0.5f, yn);
            bool sp = (v >= 1.0f);
            if (do_store) op[(size_t)(t0v + j)*(BB*HCH)] = sp ? 1.0f : 0.0f;
            v = sp ? 0.0f : v;
        }
        #pragma unroll
        for (int j = 0; j < 8; ++j) cur[j] = nxt[j];
    }
}

extern "C" void kernel_launch(void* const* d_in, const int* in_sizes, int n_in,
                              void* d_out, int out_size){
    const float* x     = (const float*)d_in[0];
    const float* w     = (const float*)d_in[1];
    const float* bias  = (const float*)d_in[2];
    const float* gamma = (const float*)d_in[3];
    const float* beta  = (const float*)d_in[4];
    float* out = (float*)d_out;

    cudaFuncSetAttribute(prep_x_kernel, cudaFuncAttributeMaxDynamicSharedMemorySize, 3*CIN*136*2);
    cudaFuncSetAttribute(conv_mma_kernel, cudaFuncAttributeMaxDynamicSharedMemorySize, SMEM_CONV);

    prep_x_kernel<<<dim3(TT_/128, BB), 256, 3*CIN*136*2>>>(x);
    prep_w_kernel<<<360, 256>>>(w);
    conv_mma_kernel<<<dim3(TT_/128, 2, BB), 256, SMEM_CONV>>>(bias);
    bn_stats_kernel<<<512, 256>>>();
    finalize_kernel<<<1, HCH>>>();
    lif_kernel<<<(BB*HCH*NCHUNK)/256, 256>>>(gamma, beta, out);
}

// round 8
// speedup vs baseline: 1.5183x; 1.5183x over previous
#include <cuda_runtime.h>
#include <cuda_bf16.h>
#include <cstdint>
#include <math.h>

#define BB   32
#define TT_  2048
#define CIN  80
#define HCH  256
#define KTOT 240            // real K = CIN*3 ; padded to 256

// scratch (device globals: no allocation allowed)
__device__ float          g_y[TT_*BB*HCH];                 // conv out (T,B,H), 64MB
__device__ unsigned short g_xk[3u*BB*256u*TT_];            // pre-shifted im2col limbs [l][b][kl(256)][t], 100.7MB
__device__ __align__(16) unsigned int g_wf2[98304];        // w fragment images [hh][kst16][nf16][l3][lane][r]
__device__ double g_sum[HCH];
__device__ double g_sumsq[HCH];
__device__ float  g_mean[HCH];
__device__ float  g_rs[HCH];

__device__ __forceinline__ uint32_t smem_u32(const void* p){
    uint32_t a; asm("{ .reg .u64 t; cvta.to.shared.u64 t, %1; cvt.u32.u64 %0, t; }" : "=r"(a) : "l"(p));
    return a;
}
__device__ __forceinline__ void lds64(uint32_t* r, uint32_t addr){
    asm volatile("ld.shared.v2.b32 {%0,%1}, [%2];" : "=r"(r[0]), "=r"(r[1]) : "r"(addr));
}
#define LDSM4T(r, a) \
    asm volatile("ldmatrix.sync.aligned.m8n8.x4.trans.shared.b16 {%0,%1,%2,%3}, [%4];" \
        : "=r"((r)[0]), "=r"((r)[1]), "=r"((r)[2]), "=r"((r)[3]) : "r"(a))
__device__ __forceinline__ void mma_bf16(float* c, const uint32_t* a, const uint32_t* b){
    asm volatile("mma.sync.aligned.m16n8k16.row.col.f32.bf16.bf16.f32 "
        "{%0,%1,%2,%3}, {%4,%5,%6,%7}, {%8,%9}, {%0,%1,%2,%3};"
        : "+f"(c[0]), "+f"(c[1]), "+f"(c[2]), "+f"(c[3])
        : "r"(a[0]), "r"(a[1]), "r"(a[2]), "r"(a[3]), "r"(b[0]), "r"(b[1]));
}
__device__ __forceinline__ void cpa16(uint32_t dst, const void* src){
    asm volatile("cp.async.cg.shared.global [%0], [%1], 16;" :: "r"(dst), "l"(src) : "memory");
}
#define CPA_COMMIT() asm volatile("cp.async.commit_group;" ::: "memory")
#define CPA_WAIT1()  asm volatile("cp.async.wait_group 1;" ::: "memory")
#define CPA_WAIT0()  asm volatile("cp.async.wait_group 0;" ::: "memory")

__device__ __forceinline__ unsigned short bsplit(float x, int s){
    __nv_bfloat16 b0 = __float2bfloat16(x);
    if (s == 0) return __bfloat16_as_ushort(b0);
    float r1 = x - __bfloat162float(b0);
    __nv_bfloat16 b1 = __float2bfloat16(r1);
    if (s == 1) return __bfloat16_as_ushort(b1);
    float r2 = r1 - __bfloat162float(b1);
    return __bfloat16_as_ushort(__float2bfloat16(r2));
}

// ---------------- prep: x -> pre-shifted im2col bf16 limb tensor ----------------
__global__ void prep_x_kernel(const float* __restrict__ x){
    extern __shared__ unsigned short sl[];   // [3][80][132]
    const int b = blockIdx.y, t0 = blockIdx.x*128, tid = threadIdx.x;
    for (int i = tid; i < 131*CIN; i += 256){
        int p = i/CIN, c = i - p*CIN;
        int t = t0 - 1 + p;
        float v = (t >= 0 && t < TT_) ? x[((size_t)b*TT_ + t)*CIN + c] : 0.f;
        __nv_bfloat16 l0 = __float2bfloat16(v);
        float r1 = v - __bfloat162float(l0);
        __nv_bfloat16 l1 = __float2bfloat16(r1);
        float r2 = r1 - __bfloat162float(l1);
        __nv_bfloat16 l2 = __float2bfloat16(r2);
        sl[(0*CIN + c)*132 + p] = __bfloat16_as_ushort(l0);
        sl[(1*CIN + c)*132 + p] = __bfloat16_as_ushort(l1);
        sl[(2*CIN + c)*132 + p] = __bfloat16_as_ushort(l2);
    }
    __syncthreads();
    uint32_t* dst = (uint32_t*)g_xk;
    for (int i = tid; i < 3*256*64; i += 256){
        int j2 = i & 63, row = i >> 6;
        int l = row >> 8, klr = row & 255;
        uint32_t vv = 0;
        if (klr < KTOT){
            int c = (klr*171) >> 9, kk = klr - 3*c;
            int base = (l*CIN + c)*132 + kk;
            uint32_t v0 = sl[base + 2*j2];
            uint32_t v1 = sl[base + 2*j2 + 1];
            vv = v0 | (v1 << 16);
        }
        dst[((size_t)(l*BB + b)*256 + klr)*1024 + (t0 >> 1) + j2] = vv;
    }
}

// ---------------- prep: w -> fragment images (kst-major), zero BN sums ----------------
__global__ void prep_w_kernel(const float* __restrict__ w){
    int i = blockIdx.x*256 + threadIdx.x;
    if (i < HCH){ g_sum[i] = 0.0; g_sumsq[i] = 0.0; }
    if (i >= 98304) return;
    int r    = i & 1;
    int lane = (i >> 1) & 31;
    int rest = i >> 6;
    int l   = rest % 3;  rest /= 3;
    int nf  = rest & 15; rest >>= 4;
    int kst = rest & 15;
    int hh  = rest >> 4;
    uint32_t vv = 0;
    if (kst < 15){
        int n  = hh*128 + nf*8 + (lane >> 2);
        int k0 = kst*16 + (lane & 3)*2 + r*8;
        int c0 = (k0*171) >> 9, kk0 = k0 - 3*c0;
        int k1 = k0 + 1;
        int c1 = (k1*171) >> 9, kk1 = k1 - 3*c1;
        uint32_t v0 = bsplit(w[(size_t)n*KTOT + c0*3 + kk0], l);
        uint32_t v1 = bsplit(w[(size_t)n*KTOT + c1*3 + kk1], l);
        vv = v0 | (v1 << 16);
    }
    g_wf2[i] = vv;
}

// ---------------- conv via mma.sync bf16 6-GEMM, cp.async double-buffered ----------------
// CTA 512 thr (16 warps, 4m x 4n, warp tile 32x32), tile 128m x 128n, K = 8 chunks of 32
#define ABUF 26112u          // 3 limbs * 32 rows * 272B
#define BBUF 24576u          // 2 ks * 16 nf * 3 l * 256B
#define BBASE (2u*ABUF)      // 52224
#define SMEM_CONV (2*ABUF + 2*BBUF)   // 101376

__global__ void __launch_bounds__(512, 1) conv_mma_kernel(const float* __restrict__ bias){
    extern __shared__ char smem[];
    const uint32_t sb = smem_u32(smem);
    const int tid = threadIdx.x, lane = tid & 31, w = tid >> 5;
    const int wm = w >> 2, wn = w & 3;
    const int t0 = blockIdx.x * 128;
    const int hh = blockIdx.y;
    const int b  = blockIdx.z;

    float acc[2][4][4];
    #pragma unroll
    for (int mf = 0; mf < 2; ++mf)
        #pragma unroll
        for (int nf = 0; nf < 4; ++nf)
            #pragma unroll
            for (int q = 0; q < 4; ++q) acc[mf][nf][q] = 0.f;

    // lane-dependent ldmatrix base: row_sub = ((lane>>4)<<3)|(lane&7), col = wm*32 + ((lane>>3)&1)*8
    const uint32_t laneA = ((((lane >> 4) << 3) | (lane & 7)) * 272u)
                         + (uint32_t)(wm*32 + ((lane >> 3) & 1)*8) * 2u;

    auto prefetch = [&](int c, int buf){
        #pragma unroll
        for (int k = 0; k < 3; ++k){
            int j = tid + k*512;
            int row = j >> 4, seg = j & 15;
            int l = row >> 5, klr = row & 31;
            const char* src = (const char*)g_xk
                + (((((size_t)l*BB + b)*256 + (c*32 + klr))*2048 + t0) << 1) + seg*16;
            cpa16(sb + (uint32_t)buf*ABUF + (uint32_t)l*8704u + (uint32_t)klr*272u + (uint32_t)seg*16u, src);
        }
        const char* bs = (const char*)g_wf2 + (size_t)(hh*16 + c*2)*12288u;   // FIX: 12288B per kst-block
        #pragma unroll
        for (int k = 0; k < 3; ++k){
            int j = tid + k*512;
            cpa16(sb + BBASE + (uint32_t)buf*BBUF + (uint32_t)j*16u, bs + (size_t)j*16);
        }
        CPA_COMMIT();
    };

    prefetch(0, 0);
    for (int c = 0; c < 8; ++c){
        const int buf = c & 1;
        if (c < 7){ prefetch(c+1, buf^1); CPA_WAIT1(); } else { CPA_WAIT0(); }
        __syncthreads();
        const uint32_t aT = sb + (uint32_t)buf*ABUF + laneA;
        const uint32_t bT = sb + BBASE + (uint32_t)buf*BBUF + (uint32_t)(wn*4*3)*256u + (uint32_t)lane*8u;
        #pragma unroll
        for (int ks = 0; ks < 2; ++ks){
            uint32_t A0[2][4], A1[2][4], A2[2][4], B0[4][2], B1[4][2], B2[4][2];
            #pragma unroll
            for (int mf = 0; mf < 2; ++mf){
                uint32_t a = aT + (uint32_t)ks*4352u + (uint32_t)mf*32u;
                LDSM4T(A0[mf], a);
                LDSM4T(A1[mf], a + 8704u);
                LDSM4T(A2[mf], a + 17408u);
            }
            #pragma unroll
            for (int nf = 0; nf < 4; ++nf){
                uint32_t ba = bT + (uint32_t)(ks*48 + nf*3)*256u;
                lds64(B0[nf], ba);
                lds64(B1[nf], ba + 256u);
                lds64(B2[nf], ba + 512u);
            }
            // per-accumulator pass order (bitwise-matches R6): 00,01,10,11,02,20
            #pragma unroll
            for (int mf = 0; mf < 2; ++mf)
                #pragma unroll
                for (int nf = 0; nf < 4; ++nf){
                    mma_bf16(acc[mf][nf], A0[mf], B0[nf]);
                    mma_bf16(acc[mf][nf], A0[mf], B1[nf]);
                    mma_bf16(acc[mf][nf], A1[mf], B0[nf]);
                    mma_bf16(acc[mf][nf], A1[mf], B1[nf]);
                    mma_bf16(acc[mf][nf], A0[mf], B2[nf]);
                    mma_bf16(acc[mf][nf], A2[mf], B0[nf]);
                }
        }
        __syncthreads();
    }

    // epilogue: acc + bias -> g_y (same numerics as R6)
    const int rbase = t0 + wm*32;
    const int hbase = hh*128 + wn*32;
    #pragma unroll
    for (int mf = 0; mf < 2; ++mf){
        int m0 = rbase + mf*16 + (lane >> 2);
        #pragma unroll
        for (int nf = 0; nf < 4; ++nf){
            int n = hbase + nf*8 + (lane & 3)*2;
            float2 bv = *(const float2*)(bias + n);
            float2 o0 = make_float2(acc[mf][nf][0] + bv.x, acc[mf][nf][1] + bv.y);
            float2 o1 = make_float2(acc[mf][nf][2] + bv.x, acc[mf][nf][3] + bv.y);
            *(float2*)(g_y + ((size_t)m0*BB + b)*HCH + n)     = o0;
            *(float2*)(g_y + ((size_t)(m0+8)*BB + b)*HCH + n) = o1;
        }
    }
}

// ---------------- BN stats (identical math; wide MLP) ----------------
__global__ void bn_stats_kernel(){
    int h = threadIdx.x;
    size_t r0 = (size_t)blockIdx.x * 128;
    const float* yp = g_y + r0*HCH + h;
    float s = 0.f, q = 0.f;
    for (int ii = 0; ii < 128; ii += 16){
        float v[16];
        #pragma unroll
        for (int j = 0; j < 16; ++j) v[j] = yp[(size_t)(ii + j)*HCH];
        #pragma unroll
        for (int j = 0; j < 16; ++j){ s += v[j]; q += v[j]*v[j]; }
    }
    atomicAdd(&g_sum[h], (double)s);
    atomicAdd(&g_sumsq[h], (double)q);
}

// ---------------- BN finalize ----------------
__global__ void finalize_kernel(){
    int h = threadIdx.x;
    const double n = (double)(TT_*BB);
    double mu  = g_sum[h] / n;
    double var = g_sumsq[h] / n - mu*mu;
    g_mean[h] = (float)mu;
    g_rs[h]   = (float)(1.0 / sqrt(var + 1e-5));
}

// ---------------- LIF recurrence (unchanged) ----------------
#define CHUNK 128
#define WARM  96
#define NCHUNK (TT_/CHUNK)
__global__ void __launch_bounds__(256) lif_kernel(const float* __restrict__ gamma,
                                                  const float* __restrict__ beta,
                                                  float* __restrict__ out){
    int g    = blockIdx.x*256 + threadIdx.x;
    int lane = g & (BB*HCH - 1);
    int chunk = g >> 13;
    int h = lane & 255;

    float mu = g_mean[h], rs = g_rs[h], ga = gamma[h], be = beta[h];
    int tstart = chunk * CHUNK;
    int tw = (chunk == 0) ? 0 : tstart - WARM;
    int tend = tstart + CHUNK;

    const float* yp = g_y + lane;
    float* op = out + lane;
    float v = 0.f;

    float cur[8], nxt[8];
    #pragma unroll
    for (int j = 0; j < 8; ++j) cur[j] = yp[(size_t)(tw + j)*(BB*HCH)];

    for (int t0v = tw; t0v < tend; t0v += 8){
        int tn = t0v + 8;
        if (tn < tend){
            #pragma unroll
            for (int j = 0; j < 8; ++j) nxt[j] = yp[(size_t)(tn + j)*(BB*HCH)];
        }
        bool do_store = (t0v >= tstart);
        #pragma unroll
        for (int j = 0; j < 8; ++j){
            float yn = fmaf((cur[j] - mu)*rs, ga, be);
            v = fmaf(v, 0.5f, yn);
            bool sp = (v >= 1.0f);
            if (do_store) op[(size_t)(t0v + j)*(BB*HCH)] = sp ? 1.0f : 0.0f;
            v = sp ? 0.0f : v;
        }
        #pragma unroll
        for (int j = 0; j < 8; ++j) cur[j] = nxt[j];
    }
}

extern "C" void kernel_launch(void* const* d_in, const int* in_sizes, int n_in,
                              void* d_out, int out_size){
    const float* x     = (const float*)d_in[0];
    const float* w     = (const float*)d_in[1];
    const float* bias  = (const float*)d_in[2];
    const float* gamma = (const float*)d_in[3];
    const float* beta  = (const float*)d_in[4];
    float* out = (float*)d_out;

    cudaFuncSetAttribute(prep_x_kernel, cudaFuncAttributeMaxDynamicSharedMemorySize, 3*CIN*132*2);
    cudaFuncSetAttribute(conv_mma_kernel, cudaFuncAttributeMaxDynamicSharedMemorySize, SMEM_CONV);

    prep_x_kernel<<<dim3(TT_/128, BB), 256, 3*CIN*132*2>>>(x);
    prep_w_kernel<<<384, 256>>>(w);
    conv_mma_kernel<<<dim3(TT_/128, 2, BB), 512, SMEM_CONV>>>(bias);
    bn_stats_kernel<<<512, 256>>>();
    finalize_kernel<<<1, HCH>>>();
    lif_kernel<<<(BB*HCH*NCHUNK)/256, 256>>>(gamma, beta, out);
}

// round 9
// speedup vs baseline: 1.5930x; 1.0492x over previous
#include <cuda_runtime.h>
#include <cuda_bf16.h>
#include <cstdint>
#include <math.h>

#define BB   32
#define TT_  2048
#define CIN  80
#define HCH  256
#define KTOT 240            // real K = CIN*3 ; padded to 256 in g_xk layout

// scratch (device globals: no allocation allowed)
__device__ float          g_y[TT_*BB*HCH];                 // conv out (T,B,H), 64MB
__device__ unsigned short g_xk[3u*BB*256u*TT_];            // pre-shifted im2col limbs [l][b][kl(256)][t], 100.7MB
__device__ __align__(16) unsigned int g_wf2[98304];        // w fragment images [hh][kst16][nf16][l3][lane][r]
__device__ double g_sum[HCH];
__device__ double g_sumsq[HCH];
__device__ float  g_mean[HCH];
__device__ float  g_rs[HCH];

__device__ __forceinline__ uint32_t smem_u32(const void* p){
    uint32_t a; asm("{ .reg .u64 t; cvta.to.shared.u64 t, %1; cvt.u32.u64 %0, t; }" : "=r"(a) : "l"(p));
    return a;
}
__device__ __forceinline__ void lds64(uint32_t* r, uint32_t addr){
    asm volatile("ld.shared.v2.b32 {%0,%1}, [%2];" : "=r"(r[0]), "=r"(r[1]) : "r"(addr));
}
#define LDSM4T(r, a) \
    asm volatile("ldmatrix.sync.aligned.m8n8.x4.trans.shared.b16 {%0,%1,%2,%3}, [%4];" \
        : "=r"((r)[0]), "=r"((r)[1]), "=r"((r)[2]), "=r"((r)[3]) : "r"(a))
__device__ __forceinline__ void mma_bf16(float* c, const uint32_t* a, const uint32_t* b){
    asm volatile("mma.sync.aligned.m16n8k16.row.col.f32.bf16.bf16.f32 "
        "{%0,%1,%2,%3}, {%4,%5,%6,%7}, {%8,%9}, {%0,%1,%2,%3};"
        : "+f"(c[0]), "+f"(c[1]), "+f"(c[2]), "+f"(c[3])
        : "r"(a[0]), "r"(a[1]), "r"(a[2]), "r"(a[3]), "r"(b[0]), "r"(b[1]));
}
__device__ __forceinline__ void cpa16(uint32_t dst, const void* src){
    asm volatile("cp.async.cg.shared.global [%0], [%1], 16;" :: "r"(dst), "l"(src) : "memory");
}
#define CPA_COMMIT() asm volatile("cp.async.commit_group;" ::: "memory")
#define CPA_WAIT1()  asm volatile("cp.async.wait_group 1;" ::: "memory")
#define CPA_WAIT0()  asm volatile("cp.async.wait_group 0;" ::: "memory")

__device__ __forceinline__ unsigned short bsplit(float x, int s){
    __nv_bfloat16 b0 = __float2bfloat16(x);
    if (s == 0) return __bfloat16_as_ushort(b0);
    float r1 = x - __bfloat162float(b0);
    __nv_bfloat16 b1 = __float2bfloat16(r1);
    if (s == 1) return __bfloat16_as_ushort(b1);
    float r2 = r1 - __bfloat162float(b1);
    return __bfloat16_as_ushort(__float2bfloat16(r2));
}

// ---------------- prep: x -> pre-shifted im2col bf16 limb tensor ----------------
__global__ void prep_x_kernel(const float* __restrict__ x){
    extern __shared__ unsigned short sl[];   // [3][80][132]
    const int b = blockIdx.y, t0 = blockIdx.x*128, tid = threadIdx.x;
    for (int i = tid; i < 131*CIN; i += 256){
        int p = i/CIN, c = i - p*CIN;
        int t = t0 - 1 + p;
        float v = (t >= 0 && t < TT_) ? x[((size_t)b*TT_ + t)*CIN + c] : 0.f;
        __nv_bfloat16 l0 = __float2bfloat16(v);
        float r1 = v - __bfloat162float(l0);
        __nv_bfloat16 l1 = __float2bfloat16(r1);
        float r2 = r1 - __bfloat162float(l1);
        __nv_bfloat16 l2 = __float2bfloat16(r2);
        sl[(0*CIN + c)*132 + p] = __bfloat16_as_ushort(l0);
        sl[(1*CIN + c)*132 + p] = __bfloat16_as_ushort(l1);
        sl[(2*CIN + c)*132 + p] = __bfloat16_as_ushort(l2);
    }
    __syncthreads();
    uint32_t* dst = (uint32_t*)g_xk;
    for (int i = tid; i < 3*256*64; i += 256){
        int j2 = i & 63, row = i >> 6;
        int l = row >> 8, klr = row & 255;
        uint32_t vv = 0;
        if (klr < KTOT){
            int c = (klr*171) >> 9, kk = klr - 3*c;
            int base = (l*CIN + c)*132 + kk;
            uint32_t v0 = sl[base + 2*j2];
            uint32_t v1 = sl[base + 2*j2 + 1];
            vv = v0 | (v1 << 16);
        }
        dst[((size_t)(l*BB + b)*256 + klr)*1024 + (t0 >> 1) + j2] = vv;
    }
}

// ---------------- prep: w -> fragment images (kst-major), zero BN sums ----------------
__global__ void prep_w_kernel(const float* __restrict__ w){
    int i = blockIdx.x*256 + threadIdx.x;
    if (i < HCH){ g_sum[i] = 0.0; g_sumsq[i] = 0.0; }
    if (i >= 98304) return;
    int r    = i & 1;
    int lane = (i >> 1) & 31;
    int rest = i >> 6;
    int l   = rest % 3;  rest /= 3;
    int nf  = rest & 15; rest >>= 4;
    int kst = rest & 15;
    int hh  = rest >> 4;
    uint32_t vv = 0;
    if (kst < 15){
        int n  = hh*128 + nf*8 + (lane >> 2);
        int k0 = kst*16 + (lane & 3)*2 + r*8;
        int c0 = (k0*171) >> 9, kk0 = k0 - 3*c0;
        int k1 = k0 + 1;
        int c1 = (k1*171) >> 9, kk1 = k1 - 3*c1;
        uint32_t v0 = bsplit(w[(size_t)n*KTOT + c0*3 + kk0], l);
        uint32_t v1 = bsplit(w[(size_t)n*KTOT + c1*3 + kk1], l);
        vv = v0 | (v1 << 16);
    }
    g_wf2[i] = vv;
}

// ---------------- conv via mma.sync bf16 6-GEMM, cp.async double-buffered ----------------
// CTA 512 thr (16 warps, 4m x 4n, warp tile 32x32), tile 128m x 128n
// K = 7 chunks of 32 + 1 chunk of 16 (kst 15 is zero padding: MMAs skipped, bitwise no-op)
#define ABUF 26112u          // 3 limbs * 32 rows * 272B
#define BBUF 24576u          // 2 ks * 16 nf * 3 l * 256B
#define BBASE (2u*ABUF)      // 52224
#define SMEM_CONV (2*ABUF + 2*BBUF)   // 101376

__global__ void __launch_bounds__(512, 1) conv_mma_kernel(const float* __restrict__ bias){
    extern __shared__ char smem[];
    const uint32_t sb = smem_u32(smem);
    const int tid = threadIdx.x, lane = tid & 31, w = tid >> 5;
    const int wm = w >> 2, wn = w & 3;
    const int t0 = blockIdx.x * 128;
    const int hh = blockIdx.y;
    const int b  = blockIdx.z;

    float acc[2][4][4];
    #pragma unroll
    for (int mf = 0; mf < 2; ++mf)
        #pragma unroll
        for (int nf = 0; nf < 4; ++nf)
            #pragma unroll
            for (int q = 0; q < 4; ++q) acc[mf][nf][q] = 0.f;

    const uint32_t laneA = ((((lane >> 4) << 3) | (lane & 7)) * 272u)
                         + (uint32_t)(wm*32 + ((lane >> 3) & 1)*8) * 2u;

    auto prefetch = [&](int c, int buf){
        #pragma unroll
        for (int k = 0; k < 3; ++k){
            int j = tid + k*512;
            int row = j >> 4, seg = j & 15;
            int l = row >> 5, klr = row & 31;
            const char* src = (const char*)g_xk
                + (((((size_t)l*BB + b)*256 + (c*32 + klr))*2048 + t0) << 1) + seg*16;
            cpa16(sb + (uint32_t)buf*ABUF + (uint32_t)l*8704u + (uint32_t)klr*272u + (uint32_t)seg*16u, src);
        }
        const char* bs = (const char*)g_wf2 + (size_t)(hh*16 + c*2)*12288u;
        #pragma unroll
        for (int k = 0; k < 3; ++k){
            int j = tid + k*512;
            cpa16(sb + BBASE + (uint32_t)buf*BBUF + (uint32_t)j*16u, bs + (size_t)j*16);
        }
        CPA_COMMIT();
    };

    auto kstep = [&](int ks, uint32_t aT, uint32_t bT){
        uint32_t A0[2][4], A1[2][4], A2[2][4], B0[4][2], B1[4][2], B2[4][2];
        #pragma unroll
        for (int mf = 0; mf < 2; ++mf){
            uint32_t a = aT + (uint32_t)ks*4352u + (uint32_t)mf*32u;
            LDSM4T(A0[mf], a);
            LDSM4T(A1[mf], a + 8704u);
            LDSM4T(A2[mf], a + 17408u);
        }
        #pragma unroll
        for (int nf = 0; nf < 4; ++nf){
            uint32_t ba = bT + (uint32_t)(ks*48 + nf*3)*256u;
            lds64(B0[nf], ba);
            lds64(B1[nf], ba + 256u);
            lds64(B2[nf], ba + 512u);
        }
        // per-accumulator limb pass order (bitwise-stable): 00,01,10,11,02,20
        #pragma unroll
        for (int mf = 0; mf < 2; ++mf)
            #pragma unroll
            for (int nf = 0; nf < 4; ++nf){
                mma_bf16(acc[mf][nf], A0[mf], B0[nf]);
                mma_bf16(acc[mf][nf], A0[mf], B1[nf]);
                mma_bf16(acc[mf][nf], A1[mf], B0[nf]);
                mma_bf16(acc[mf][nf], A1[mf], B1[nf]);
                mma_bf16(acc[mf][nf], A0[mf], B2[nf]);
                mma_bf16(acc[mf][nf], A2[mf], B0[nf]);
            }
    };

    prefetch(0, 0);
    for (int c = 0; c < 8; ++c){
        const int buf = c & 1;
        if (c < 7){ prefetch(c+1, buf^1); CPA_WAIT1(); } else { CPA_WAIT0(); }
        __syncthreads();
        const uint32_t aT = sb + (uint32_t)buf*ABUF + laneA;
        const uint32_t bT = sb + BBASE + (uint32_t)buf*BBUF + (uint32_t)(wn*4*3)*256u + (uint32_t)lane*8u;
        kstep(0, aT, bT);
        if (c < 7) kstep(1, aT, bT);     // kst 15 (k 240..255) is zero padding — skip
        __syncthreads();
    }

    // epilogue: acc + bias -> g_y (numerics unchanged)
    const int rbase = t0 + wm*32;
    const int hbase = hh*128 + wn*32;
    #pragma unroll
    for (int mf = 0; mf < 2; ++mf){
        int m0 = rbase + mf*16 + (lane >> 2);
        #pragma unroll
        for (int nf = 0; nf < 4; ++nf){
            int n = hbase + nf*8 + (lane & 3)*2;
            float2 bv = *(const float2*)(bias + n);
            float2 o0 = make_float2(acc[mf][nf][0] + bv.x, acc[mf][nf][1] + bv.y);
            float2 o1 = make_float2(acc[mf][nf][2] + bv.x, acc[mf][nf][3] + bv.y);
            *(float2*)(g_y + ((size_t)m0*BB + b)*HCH + n)     = o0;
            *(float2*)(g_y + ((size_t)(m0+8)*BB + b)*HCH + n) = o1;
        }
    }
}

// ---------------- BN stats: identical accumulation order, software-pipelined ----------------
__global__ void bn_stats_kernel(){
    int h = threadIdx.x;
    size_t r0 = (size_t)blockIdx.x * 128;
    const float* yp = g_y + r0*HCH + h;
    float s = 0.f, q = 0.f;
    float v[16], nx[16];
    #pragma unroll
    for (int j = 0; j < 16; ++j) v[j] = yp[(size_t)j*HCH];
    for (int ii = 0; ii < 128; ii += 16){
        if (ii < 112){
            #pragma unroll
            for (int j = 0; j < 16; ++j) nx[j] = yp[(size_t)(ii + 16 + j)*HCH];
        }
        #pragma unroll
        for (int j = 0; j < 16; ++j){ s += v[j]; q += v[j]*v[j]; }
        #pragma unroll
        for (int j = 0; j < 16; ++j) v[j] = nx[j];
    }
    atomicAdd(&g_sum[h], (double)s);
    atomicAdd(&g_sumsq[h], (double)q);
}

// ---------------- BN finalize ----------------
__global__ void finalize_kernel(){
    int h = threadIdx.x;
    const double n = (double)(TT_*BB);
    double mu  = g_sum[h] / n;
    double var = g_sumsq[h] / n - mu*mu;
    g_mean[h] = (float)mu;
    g_rs[h]   = (float)(1.0 / sqrt(var + 1e-5));
}

// ---------------- LIF recurrence: same math, 16-deep double-buffered loads ----------------
#define CHUNK 128
#define WARM  96
#define NCHUNK (TT_/CHUNK)
__global__ void __launch_bounds__(256) lif_kernel(const float* __restrict__ gamma,
                                                  const float* __restrict__ beta,
                                                  float* __restrict__ out){
    int g    = blockIdx.x*256 + threadIdx.x;
    int lane = g & (BB*HCH - 1);
    int chunk = g >> 13;
    int h = lane & 255;

    float mu = g_mean[h], rs = g_rs[h], ga = gamma[h], be = beta[h];
    int tstart = chunk * CHUNK;
    int tw = (chunk == 0) ? 0 : tstart - WARM;
    int tend = tstart + CHUNK;

    const float* yp = g_y + lane;
    float* op = out + lane;
    float v = 0.f;

    float cur[16], nxt[16];
    #pragma unroll
    for (int j = 0; j < 16; ++j) cur[j] = yp[(size_t)(tw + j)*(BB*HCH)];

    for (int t0v = tw; t0v < tend; t0v += 16){
        int tn = t0v + 16;
        if (tn < tend){
            #pragma unroll
            for (int j = 0; j < 16; ++j) nxt[j] = yp[(size_t)(tn + j)*(BB*HCH)];
        }
        bool do_store = (t0v >= tstart);
        #pragma unroll
        for (int j = 0; j < 16; ++j){
            float yn = fmaf((cur[j] - mu)*rs, ga, be);
            v = fmaf(v, 0.5f, yn);
            bool sp = (v >= 1.0f);
            if (do_store) op[(size_t)(t0v + j)*(BB*HCH)] = sp ? 1.0f : 0.0f;
            v = sp ? 0.0f : v;
        }
        #pragma unroll
        for (int j = 0; j < 16; ++j) cur[j] = nxt[j];
    }
}

extern "C" void kernel_launch(void* const* d_in, const int* in_sizes, int n_in,
                              void* d_out, int out_size){
    const float* x     = (const float*)d_in[0];
    const float* w     = (const float*)d_in[1];
    const float* bias  = (const float*)d_in[2];
    const float* gamma = (const float*)d_in[3];
    const float* beta  = (const float*)d_in[4];
    float* out = (float*)d_out;

    cudaFuncSetAttribute(prep_x_kernel, cudaFuncAttributeMaxDynamicSharedMemorySize, 3*CIN*132*2);
    cudaFuncSetAttribute(conv_mma_kernel, cudaFuncAttributeMaxDynamicSharedMemorySize, SMEM_CONV);

    prep_x_kernel<<<dim3(TT_/128, BB), 256, 3*CIN*132*2>>>(x);
    prep_w_kernel<<<384, 256>>>(w);
    conv_mma_kernel<<<dim3(TT_/128, 2, BB), 512, SMEM_CONV>>>(bias);
    bn_stats_kernel<<<512, 256>>>();
    finalize_kernel<<<1, HCH>>>();
    lif_kernel<<<(BB*HCH*NCHUNK)/256, 256>>>(gamma, beta, out);
}